// round 10
// baseline (speedup 1.0000x reference)
#include <cuda_runtime.h>
#include <cstdint>

#define NB     16
#define NROWS  128
#define NT     128
#define NVOCAB 258
typedef unsigned long long u64;

// ---------------- static device scratch ----------------
__device__ __align__(16) float  g_proj[NVOCAB * 96];
__device__ __align__(16) float4 g_w4[3 * 2 * 3 * 8 * 32];    // [l][side][gate][chunk][j]
__device__ __align__(16) float  g_cbias[96];
__device__ __align__(16) float  g_w64[96];
__device__ __align__(16) float  g_wvt[32 * NVOCAB];          // w_out^T [k][v]
__device__ __align__(16) float  g_hout[NROWS * NT * 2 * 8 * 32]; // [rt][half][b][j]
__device__ int g_flag[NROWS * 2];

// ---------------- helpers ----------------
__device__ __forceinline__ int ld_acq(const int* p) {
    int v; asm volatile("ld.acquire.gpu.s32 %0, [%1];" : "=r"(v) : "l"(p) : "memory"); return v;
}
__device__ __forceinline__ void st_rel(int* p, int v) {
    asm volatile("st.release.gpu.s32 [%0], %1;" :: "l"(p), "r"(v) : "memory");
}
__device__ __forceinline__ u64 dup2(float x) {
    u64 r; unsigned xi = __float_as_uint(x);
    asm("mov.b64 %0, {%1, %1};" : "=l"(r) : "r"(xi)); return r;
}
__device__ __forceinline__ u64 pack2(float a, float b) {
    u64 r; asm("mov.b64 %0, {%1, %2};" : "=l"(r) : "r"(__float_as_uint(a)), "r"(__float_as_uint(b)));
    return r;
}
__device__ __forceinline__ float2 unpk(u64 v) {
    unsigned lo, hi; asm("mov.b64 {%0, %1}, %2;" : "=r"(lo), "=r"(hi) : "l"(v));
    return make_float2(__uint_as_float(lo), __uint_as_float(hi));
}
__device__ __forceinline__ u64 fma2(u64 a, u64 b, u64 c) {
    u64 d; asm("fma.rn.f32x2 %0, %1, %2, %3;" : "=l"(d) : "l"(a), "l"(b), "l"(c)); return d;
}
__device__ __forceinline__ float tanh_ap(float x) {
    float y; asm("tanh.approx.f32 %0, %1;" : "=f"(y) : "f"(x)); return y;
}
__device__ __forceinline__ float sig_ap(float x) { return fmaf(tanh_ap(x * 0.5f), 0.5f, 0.5f); }

// ---------------- prep ----------------
__global__ void prep_kernel(
    const float* __restrict__ embed,
    const float* __restrict__ wih0, const float* __restrict__ whh0,
    const float* __restrict__ wih1, const float* __restrict__ whh1,
    const float* __restrict__ wih2, const float* __restrict__ whh2,
    const float* __restrict__ w_h2e, const float* __restrict__ b_h2e,
    const float* __restrict__ bih0, const float* __restrict__ w_out)
{
    const int v = blockIdx.x;
    const int g = threadIdx.x;       // 0..95
    if (v < NVOCAB) {
        float s = 0.0f;
        #pragma unroll 8
        for (int e = 0; e < 64; ++e) s = fmaf(embed[v * 64 + e], wih0[g * 65 + e], s);
        g_proj[v * 96 + g] = s;
    } else if (v == NVOCAB) {
        const int gate = g >> 5, j = g & 31;
        float cb = bih0[g];
        for (int e = 0; e < 65; ++e) cb = fmaf(wih0[g * 65 + e], b_h2e[e], cb);
        g_cbias[g] = cb;
        g_w64[g] = wih0[g * 65 + 64];
        float wc[32];
        #pragma unroll
        for (int k = 0; k < 32; ++k) {
            float s = 0.0f;
            for (int e = 0; e < 65; ++e) s = fmaf(wih0[g * 65 + e], w_h2e[e * 32 + k], s);
            wc[k] = s;
        }
        const float* Wm[3][2] = {{0, whh0}, {wih1, whh1}, {wih2, whh2}};
        #pragma unroll
        for (int c = 0; c < 8; ++c) {
            g_w4[(((0 * 2 + 0) * 3 + gate) * 8 + c) * 32 + j] =
                make_float4(wc[4*c], wc[4*c+1], wc[4*c+2], wc[4*c+3]);
            for (int l = 0; l < 3; ++l)
                for (int s_ = 0; s_ < 2; ++s_) {
                    const float* W = Wm[l][s_];
                    if (!W) continue;
                    g_w4[(((l * 2 + s_) * 3 + gate) * 8 + c) * 32 + j] =
                        make_float4(W[g*32+4*c], W[g*32+4*c+1], W[g*32+4*c+2], W[g*32+4*c+3]);
                }
        }
    } else {
        for (int i = g; i < 32 * NVOCAB; i += 96) {
            int k = i / NVOCAB, vv = i % NVOCAB;
            g_wvt[i] = w_out[vv * 32 + k];
        }
    }
}

__global__ void reset_kernel() {
    int i = threadIdx.x;
    if (i < NROWS * 2) g_flag[i] = 0;
}

// ---------------- persistent wavefront: CTA=(row,half8), warp=gate ----------------
__global__ __launch_bounds__(96) void rnn_kernel(
    const int* __restrict__ x,
    const float* __restrict__ bhh0,
    const float* __restrict__ bih1, const float* __restrict__ bhh1,
    const float* __restrict__ bih2, const float* __restrict__ bhh2)
{
    __shared__ __align__(16) float hsm[4][8][32];   // slots: prev, h0, h1, h2
    __shared__ float rsh[8][32], zsh[8][32];
    __shared__ int toksh[8][NT];

    const int tid  = threadIdx.x;
    const int g    = tid >> 5;           // 0=r, 1=z, 2=n
    const int j    = tid & 31;
    const int off  = tid;                // g*32 + j
    const int r    = blockIdx.x >> 1;
    const int half = blockIdx.x & 1;
    const int bG0  = half * 8;

    // prologue: cache row tokens, zero h buffers
    for (int idx = tid; idx < 256; idx += 96) {
        int b = idx >> 5, tq = idx & 31;
        ((int4*)&toksh[b][0])[tq] =
            __ldcg(&((const int4*)(x + (bG0 + b) * (NROWS * NT) + r * NT))[tq]);
    }
    for (int idx = tid; idx < 4 * 8 * 32; idx += 96) (&hsm[0][0][0])[idx] = 0.f;

    const float rf  = (float)r * (2.f / 128.f) - 1.f;
    const float cA0 = fmaf(rf, g_w64[off], g_cbias[off]);
    const float cA1 = bih1[off], cA2 = bih2[off];
    const float cB0 = bhh0[off], cB1 = bhh1[off], cB2 = bhh2[off];

    int*       myflag   = &g_flag[r * 2 + half];
    const int* prevflag = &g_flag[(r - 1) * 2 + half];
    __syncthreads();

    for (int t = 0; t < NT; ++t) {
        // proj loads for this step issued BEFORE the wait (latency buried in poll)
        float pf[8];
        #pragma unroll
        for (int b = 0; b < 8; ++b)
            pf[b] = __ldg(&g_proj[toksh[b][t] * 96 + off]);

        if (r > 0) {
            while (ld_acq(prevflag) < t + 1) { }
            if (tid < 64)
                ((float4*)&hsm[0][0][0])[tid] =
                    __ldcg(&((const float4*)g_hout)[(((r - 1) * NT + t) * 2 + half) * 64 + tid]);
        }
        __syncthreads();                                   // bar A

        #pragma unroll
        for (int l = 0; l < 3; ++l) {
            const float cA = (l == 0) ? cA0 : ((l == 1) ? cA1 : cA2);
            const float cB = (l == 0) ? cB0 : ((l == 1) ? cB1 : cB2);
            const ulonglong2* wi = (const ulonglong2*)(g_w4 + ((l * 2 + 0) * 3 + g) * 256);
            const ulonglong2* wh = (const ulonglong2*)(g_w4 + ((l * 2 + 1) * 3 + g) * 256);
            const float (*insm)[32] = hsm[l];              // input  = h^{l-1} (or prev)
            const float (*hdsm)[32] = hsm[l + 1];          // hidden = h^l old

            u64 acc[8], acc2[8];
            if (g < 2) {
                // r/z: single accumulator (sides merged), k-paired f32x2
                #pragma unroll
                for (int b = 0; b < 8; ++b)
                    acc[b] = pack2(cA + cB + ((l == 0) ? pf[b] : 0.f), 0.f);
                #pragma unroll
                for (int c = 0; c < 8; ++c) {
                    ulonglong2 wiv = wi[c * 32 + j];
                    ulonglong2 whv = wh[c * 32 + j];
                    #pragma unroll
                    for (int b = 0; b < 8; ++b) {
                        ulonglong2 iv = *(const ulonglong2*)&insm[b][4 * c];
                        ulonglong2 hv = *(const ulonglong2*)&hdsm[b][4 * c];
                        acc[b] = fma2(wiv.x, iv.x, acc[b]);
                        acc[b] = fma2(wiv.y, iv.y, acc[b]);
                        acc[b] = fma2(whv.x, hv.x, acc[b]);
                        acc[b] = fma2(whv.y, hv.y, acc[b]);
                    }
                }
                float* gs = (g == 0) ? &rsh[0][0] : &zsh[0][0];
                #pragma unroll
                for (int b = 0; b < 8; ++b) {
                    float2 f = unpk(acc[b]);
                    gs[b * 32 + j] = sig_ap(f.x + f.y);
                }
            } else {
                // n: separate input/hidden accumulators
                #pragma unroll
                for (int b = 0; b < 8; ++b) {
                    acc[b]  = pack2(cA + ((l == 0) ? pf[b] : 0.f), 0.f);
                    acc2[b] = pack2(cB, 0.f);
                }
                #pragma unroll
                for (int c = 0; c < 8; ++c) {
                    ulonglong2 wiv = wi[c * 32 + j];
                    ulonglong2 whv = wh[c * 32 + j];
                    #pragma unroll
                    for (int b = 0; b < 8; ++b) {
                        ulonglong2 iv = *(const ulonglong2*)&insm[b][4 * c];
                        ulonglong2 hv = *(const ulonglong2*)&hdsm[b][4 * c];
                        acc[b]  = fma2(wiv.x, iv.x, acc[b]);
                        acc[b]  = fma2(wiv.y, iv.y, acc[b]);
                        acc2[b] = fma2(whv.x, hv.x, acc2[b]);
                        acc2[b] = fma2(whv.y, hv.y, acc2[b]);
                    }
                }
            }
            __syncthreads();                               // bar B: rsh/zsh ready

            if (g == 2) {
                #pragma unroll
                for (int b = 0; b < 8; ++b) {
                    float2 fi = unpk(acc[b]);
                    float2 fh = unpk(acc2[b]);
                    float ai = fi.x + fi.y, ah = fh.x + fh.y;
                    float nn = tanh_ap(fmaf(rsh[b][j], ah, ai));
                    float hold = hsm[l + 1][b][j];
                    float hv2 = fmaf(zsh[b][j], hold - nn, nn);
                    hsm[l + 1][b][j] = hv2;
                    if (l == 2)
                        __stcg(&g_hout[((r * NT + t) * 2 + half) * 256 + b * 32 + j], hv2);
                }
            }
            __syncthreads();                               // bar C: h^l new ready
        }
        if (tid == 0) st_rel(myflag, t + 1);
    }
}

// ---------------- epilogue: block = (half, 4 rt-cells), thread = vocab scalar ----------------
__global__ __launch_bounds__(256) void out_kernel(
    float* __restrict__ outp, const float* __restrict__ b_out)
{
    __shared__ __align__(16) u64 hp[32][16];   // [k][cp]; cp = rt_i*4 + bpair
    const int tid  = threadIdx.x;
    const int half = blockIdx.x & 1;
    const int rt0  = (blockIdx.x >> 1) * 4;

    {
        int rt_i = tid >> 6, rem = tid & 63;
        float4 hv = __ldcg(&((const float4*)g_hout)[((rt0 + rt_i) * 2 + half) * 64 + rem]);
        int b = rem >> 3, kq = (rem & 7) * 4;
        int cp = rt_i * 4 + (b >> 1), hf = b & 1;
        ((float*)&hp[kq + 0][cp])[hf] = hv.x;
        ((float*)&hp[kq + 1][cp])[hf] = hv.y;
        ((float*)&hp[kq + 2][cp])[hf] = hv.z;
        ((float*)&hp[kq + 3][cp])[hf] = hv.w;
    }
    __syncthreads();

    for (int v = tid; v < NVOCAB; v += 256) {
        u64 acc[16];
        const u64 bia = dup2(__ldg(&b_out[v]));
        #pragma unroll
        for (int cp = 0; cp < 16; ++cp) acc[cp] = bia;
        #pragma unroll
        for (int k = 0; k < 32; ++k) {
            const u64 wv = dup2(__ldg(&g_wvt[k * NVOCAB + v]));
            const ulonglong2* hk = (const ulonglong2*)hp[k];
            #pragma unroll
            for (int q = 0; q < 8; ++q) {
                ulonglong2 h2 = hk[q];
                acc[2 * q + 0] = fma2(wv, h2.x, acc[2 * q + 0]);
                acc[2 * q + 1] = fma2(wv, h2.y, acc[2 * q + 1]);
            }
        }
        #pragma unroll
        for (int cp = 0; cp < 16; ++cp) {
            int rt_i = cp >> 2, bp = cp & 3;
            long rt = rt0 + rt_i;
            long b0 = half * 8 + 2 * bp;
            float2 o = unpk(acc[cp]);
            outp[(b0 * (NROWS * NT) + rt) * NVOCAB + v] = o.x;
            outp[((b0 + 1) * (NROWS * NT) + rt) * NVOCAB + v] = o.y;
        }
    }
}

// ---------------- launch ----------------
extern "C" void kernel_launch(void* const* d_in, const int* in_sizes, int n_in,
                              void* d_out, int out_size)
{
    (void)in_sizes; (void)n_in; (void)out_size;
    const int*   x     = (const int*)  d_in[0];
    const float* embed = (const float*)d_in[1];
    const float* wih0  = (const float*)d_in[2];
    const float* whh0  = (const float*)d_in[3];
    const float* bih0  = (const float*)d_in[4];
    const float* bhh0  = (const float*)d_in[5];
    const float* wih1  = (const float*)d_in[6];
    const float* whh1  = (const float*)d_in[7];
    const float* bih1  = (const float*)d_in[8];
    const float* bhh1  = (const float*)d_in[9];
    const float* wih2  = (const float*)d_in[10];
    const float* whh2  = (const float*)d_in[11];
    const float* bih2  = (const float*)d_in[12];
    const float* bhh2  = (const float*)d_in[13];
    const float* w_h2e = (const float*)d_in[14];
    const float* b_h2e = (const float*)d_in[15];
    const float* w_out = (const float*)d_in[16];
    const float* b_out = (const float*)d_in[17];
    float* outp = (float*)d_out;

    prep_kernel<<<260, 96>>>(embed, wih0, whh0, wih1, whh1, wih2, whh2,
                             w_h2e, b_h2e, bih0, w_out);
    reset_kernel<<<1, 256>>>();
    rnn_kernel<<<NROWS * 2, 96>>>(x, bhh0, bih1, bhh1, bih2, bhh2);
    out_kernel<<<(NROWS * NT / 4) * 2, 256>>>(outp, b_out);
}

// round 12
// speedup vs baseline: 1.9626x; 1.9626x over previous
#include <cuda_runtime.h>
#include <cstdint>

#define NB     16
#define NROWS  128
#define NT     128
#define NVOCAB 258
typedef unsigned long long u64;

// ---------------- static device scratch ----------------
__device__ __align__(16) float  g_proj[NVOCAB * 96];
__device__ __align__(16) float4 g_w4[3 * 2 * 3 * 8 * 32];    // [l][side][gate][chunk][j]
__device__ __align__(16) float  g_cbias[96];
__device__ __align__(16) float  g_w64[96];
__device__ __align__(16) float  g_wvt[32 * NVOCAB];          // w_out^T [k][v]
__device__ __align__(16) float  g_hout[NROWS * NT * 2 * 8 * 32]; // [rt][half][b][j]
__device__ int g_flag[NROWS * 2];

// ---------------- helpers ----------------
__device__ __forceinline__ int ld_acq(const int* p) {
    int v; asm volatile("ld.acquire.gpu.s32 %0, [%1];" : "=r"(v) : "l"(p) : "memory"); return v;
}
__device__ __forceinline__ void st_rel(int* p, int v) {
    asm volatile("st.release.gpu.s32 [%0], %1;" :: "l"(p), "r"(v) : "memory");
}
__device__ __forceinline__ u64 dup2(float x) {
    u64 r; unsigned xi = __float_as_uint(x);
    asm("mov.b64 %0, {%1, %1};" : "=l"(r) : "r"(xi)); return r;
}
__device__ __forceinline__ u64 pack2(float a, float b) {
    u64 r; asm("mov.b64 %0, {%1, %2};" : "=l"(r) : "r"(__float_as_uint(a)), "r"(__float_as_uint(b)));
    return r;
}
__device__ __forceinline__ float2 unpk(u64 v) {
    unsigned lo, hi; asm("mov.b64 {%0, %1}, %2;" : "=r"(lo), "=r"(hi) : "l"(v));
    return make_float2(__uint_as_float(lo), __uint_as_float(hi));
}
__device__ __forceinline__ u64 fma2(u64 a, u64 b, u64 c) {
    u64 d; asm("fma.rn.f32x2 %0, %1, %2, %3;" : "=l"(d) : "l"(a), "l"(b), "l"(c)); return d;
}
__device__ __forceinline__ float tanh_ap(float x) {
    float y; asm("tanh.approx.f32 %0, %1;" : "=f"(y) : "f"(x)); return y;
}
__device__ __forceinline__ float sig_ap(float x) { return fmaf(tanh_ap(x * 0.5f), 0.5f, 0.5f); }

// ---------------- prep ----------------
__global__ void prep_kernel(
    const float* __restrict__ embed,
    const float* __restrict__ wih0, const float* __restrict__ whh0,
    const float* __restrict__ wih1, const float* __restrict__ whh1,
    const float* __restrict__ wih2, const float* __restrict__ whh2,
    const float* __restrict__ w_h2e, const float* __restrict__ b_h2e,
    const float* __restrict__ bih0, const float* __restrict__ w_out)
{
    const int v = blockIdx.x;
    const int g = threadIdx.x;       // 0..95
    if (v < NVOCAB) {
        float s = 0.0f;
        #pragma unroll 8
        for (int e = 0; e < 64; ++e) s = fmaf(embed[v * 64 + e], wih0[g * 65 + e], s);
        g_proj[v * 96 + g] = s;
    } else if (v == NVOCAB) {
        const int gate = g >> 5, j = g & 31;
        float cb = bih0[g];
        for (int e = 0; e < 65; ++e) cb = fmaf(wih0[g * 65 + e], b_h2e[e], cb);
        g_cbias[g] = cb;
        g_w64[g] = wih0[g * 65 + 64];
        float wc[32];
        #pragma unroll
        for (int k = 0; k < 32; ++k) {
            float s = 0.0f;
            for (int e = 0; e < 65; ++e) s = fmaf(wih0[g * 65 + e], w_h2e[e * 32 + k], s);
            wc[k] = s;
        }
        const float* Wm[3][2] = {{0, whh0}, {wih1, whh1}, {wih2, whh2}};
        #pragma unroll
        for (int c = 0; c < 8; ++c) {
            g_w4[(((0 * 2 + 0) * 3 + gate) * 8 + c) * 32 + j] =
                make_float4(wc[4*c], wc[4*c+1], wc[4*c+2], wc[4*c+3]);
            for (int l = 0; l < 3; ++l)
                for (int s_ = 0; s_ < 2; ++s_) {
                    const float* W = Wm[l][s_];
                    if (!W) continue;
                    g_w4[(((l * 2 + s_) * 3 + gate) * 8 + c) * 32 + j] =
                        make_float4(W[g*32+4*c], W[g*32+4*c+1], W[g*32+4*c+2], W[g*32+4*c+3]);
                }
        }
    } else {
        for (int i = g; i < 32 * NVOCAB; i += 96) {
            int k = i / NVOCAB, vv = i % NVOCAB;
            g_wvt[i] = w_out[vv * 32 + k];
        }
    }
}

__global__ void reset_kernel() {
    int i = threadIdx.x;
    if (i < NROWS * 2) g_flag[i] = 0;
}

// ---------------- one GRU layer from smem weights; k-pair f32x2, 2 batches ----------------
__device__ __forceinline__ void layer_step(
    const float* __restrict__ wsl,                 // layer base (6144 floats)
    const float (*__restrict__ insm)[36],
    const float (*__restrict__ hq)[36],
    float (*__restrict__ hp)[36],
    int j, int b0,
    float cr, float cz, float cn, float ch,
    float ar0, float ar1, float az0, float az1, float an0, float an1,
    float* __restrict__ hold)
{
    const ulonglong2* wir = (const ulonglong2*)(wsl)        + j;
    const ulonglong2* wiz = (const ulonglong2*)(wsl + 1024) + j;
    const ulonglong2* win = (const ulonglong2*)(wsl + 2048) + j;
    const ulonglong2* whr = (const ulonglong2*)(wsl + 3072) + j;
    const ulonglong2* whz = (const ulonglong2*)(wsl + 4096) + j;
    const ulonglong2* whn = (const ulonglong2*)(wsl + 5120) + j;
    u64 ar[2] = { pack2(cr + ar0, 0.f), pack2(cr + ar1, 0.f) };
    u64 az[2] = { pack2(cz + az0, 0.f), pack2(cz + az1, 0.f) };
    u64 ai[2] = { pack2(cn + an0, 0.f), pack2(cn + an1, 0.f) };
    u64 ah[2] = { pack2(ch, 0.f),       pack2(ch, 0.f) };
    #pragma unroll
    for (int c = 0; c < 8; ++c) {
        ulonglong2 w_ir = wir[c * 32];
        ulonglong2 w_iz = wiz[c * 32];
        ulonglong2 w_in = win[c * 32];
        ulonglong2 w_hr = whr[c * 32];
        ulonglong2 w_hz = whz[c * 32];
        ulonglong2 w_hn = whn[c * 32];
        #pragma unroll
        for (int bi = 0; bi < 2; ++bi) {
            ulonglong2 xv = *(const ulonglong2*)&insm[b0 + bi][4 * c];
            ulonglong2 hv = *(const ulonglong2*)&hq[b0 + bi][4 * c];
            ar[bi] = fma2(w_ir.x, xv.x, ar[bi]); ar[bi] = fma2(w_ir.y, xv.y, ar[bi]);
            ar[bi] = fma2(w_hr.x, hv.x, ar[bi]); ar[bi] = fma2(w_hr.y, hv.y, ar[bi]);
            az[bi] = fma2(w_iz.x, xv.x, az[bi]); az[bi] = fma2(w_iz.y, xv.y, az[bi]);
            az[bi] = fma2(w_hz.x, hv.x, az[bi]); az[bi] = fma2(w_hz.y, hv.y, az[bi]);
            ai[bi] = fma2(w_in.x, xv.x, ai[bi]); ai[bi] = fma2(w_in.y, xv.y, ai[bi]);
            ah[bi] = fma2(w_hn.x, hv.x, ah[bi]); ah[bi] = fma2(w_hn.y, hv.y, ah[bi]);
        }
    }
    #pragma unroll
    for (int bi = 0; bi < 2; ++bi) {
        float2 fr = unpk(ar[bi]), fz = unpk(az[bi]);
        float2 fi = unpk(ai[bi]), fh = unpk(ah[bi]);
        float rr = sig_ap(fr.x + fr.y), zz = sig_ap(fz.x + fz.y);
        float nn = tanh_ap(fmaf(rr, fh.x + fh.y, fi.x + fi.y));
        float hv = fmaf(zz, hold[bi] - nn, nn);
        hold[bi] = hv;
        hp[b0 + bi][j] = hv;
    }
}

// ---------------- persistent wavefront: CTA=(row,half8), thread=(unit j, batch-pair) ----------------
// dyn smem layout: ws[18432] | prevsh[8][36] | hbuf[6][8][36] | toksh[8][128]
#define SMEM_RNN (73728 + 1152 + 6912 + 4096)
__global__ __launch_bounds__(128) void rnn_kernel(
    const int* __restrict__ x,
    const float* __restrict__ bhh0,
    const float* __restrict__ bih1, const float* __restrict__ bhh1,
    const float* __restrict__ bih2, const float* __restrict__ bhh2)
{
    extern __shared__ __align__(16) char smem[];
    float* ws = (float*)smem;
    float (*prevsh)[36]   = (float(*)[36])(smem + 73728);
    float (*hbuf)[8][36]  = (float(*)[8][36])(smem + 73728 + 1152);  // [l*2+parity]
    int   (*toksh)[128]   = (int(*)[128])(smem + 73728 + 1152 + 6912);

    const int tid  = threadIdx.x;
    const int j    = tid >> 2;
    const int bp   = tid & 3;
    const int b0   = 2 * bp;
    const int r    = blockIdx.x >> 1;
    const int half = blockIdx.x & 1;

    // prologue: weights -> smem (coalesced), tokens -> smem, zero h buffers
    const float4* wg = g_w4;
    for (int idx = tid; idx < 4608; idx += 128)
        ((float4*)ws)[idx] = wg[idx];
    for (int idx = tid; idx < 8 * 128; idx += 128) {
        int bb = idx >> 7, tt = idx & 127;
        toksh[bb][tt] = x[(half * 8 + bb) * (NROWS * NT) + r * NT + tt];
    }
    for (int idx = tid; idx < 8 * 36; idx += 128) (&prevsh[0][0])[idx] = 0.f;
    for (int idx = tid; idx < 6 * 8 * 36; idx += 128) (&hbuf[0][0][0])[idx] = 0.f;

    const float rf = (float)r * (2.f / 128.f) - 1.f;
    const float c_r0 = fmaf(rf, g_w64[j],      g_cbias[j])      + bhh0[j];
    const float c_z0 = fmaf(rf, g_w64[32 + j], g_cbias[32 + j]) + bhh0[32 + j];
    const float c_n0 = fmaf(rf, g_w64[64 + j], g_cbias[64 + j]);
    const float c_h0 = bhh0[64 + j];
    const float c_r1 = bih1[j] + bhh1[j];
    const float c_z1 = bih1[32 + j] + bhh1[32 + j];
    const float c_n1 = bih1[64 + j];
    const float c_h1 = bhh1[64 + j];
    const float c_r2 = bih2[j] + bhh2[j];
    const float c_z2 = bih2[32 + j] + bhh2[32 + j];
    const float c_n2 = bih2[64 + j];
    const float c_h2 = bhh2[64 + j];

    float h0old[2] = {0.f, 0.f}, h1old[2] = {0.f, 0.f}, h2old[2] = {0.f, 0.f};

    int*       myflag   = &g_flag[r * 2 + half];
    const int* prevflag = &g_flag[(r - 1) * 2 + half];
    __syncthreads();

    for (int t = 0; t < NT; ++t) {
        const int p = t & 1, q = p ^ 1;
        // proj loads issued before the wait (latency buried in poll)
        const int tk0 = toksh[b0][t], tk1 = toksh[b0 + 1][t];
        const float pr0 = __ldg(&g_proj[tk0 * 96 + j]);
        const float pz0 = __ldg(&g_proj[tk0 * 96 + 32 + j]);
        const float pn0 = __ldg(&g_proj[tk0 * 96 + 64 + j]);
        const float pr1 = __ldg(&g_proj[tk1 * 96 + j]);
        const float pz1 = __ldg(&g_proj[tk1 * 96 + 32 + j]);
        const float pn1 = __ldg(&g_proj[tk1 * 96 + 64 + j]);

        if (r > 0) {
            while (ld_acq(prevflag) < t + 1) { }
            if (tid < 64) {
                float4 pv = __ldcg(&((const float4*)g_hout)[(((r - 1) * NT + t) * 2 + half) * 64 + tid]);
                *(float4*)&prevsh[tid >> 3][(tid & 7) * 4] = pv;
            }
        }
        __syncthreads();                                       // bar A

        layer_step(ws,         prevsh,        hbuf[0 + q], hbuf[0 + p], j, b0,
                   c_r0, c_z0, c_n0, c_h0, pr0, pr1, pz0, pz1, pn0, pn1, h0old);
        __syncthreads();                                       // bar B
        layer_step(ws + 6144,  hbuf[0 + p],   hbuf[2 + q], hbuf[2 + p], j, b0,
                   c_r1, c_z1, c_n1, c_h1, 0.f, 0.f, 0.f, 0.f, 0.f, 0.f, h1old);
        __syncthreads();                                       // bar C
        layer_step(ws + 12288, hbuf[2 + p],   hbuf[4 + q], hbuf[4 + p], j, b0,
                   c_r2, c_z2, c_n2, c_h2, 0.f, 0.f, 0.f, 0.f, 0.f, 0.f, h2old);

        __stcg(&g_hout[((r * NT + t) * 2 + half) * 256 + b0 * 32 + j],       h2old[0]);
        __stcg(&g_hout[((r * NT + t) * 2 + half) * 256 + (b0 + 1) * 32 + j], h2old[1]);
        __syncthreads();                                       // bar D
        if (tid == 0) st_rel(myflag, t + 1);
    }
}

// ---------------- epilogue: block = (half, 4 rt-cells), thread = vocab scalar ----------------
__global__ __launch_bounds__(256) void out_kernel(
    float* __restrict__ outp, const float* __restrict__ b_out)
{
    __shared__ __align__(16) u64 hp[32][16];   // [k][cp]; cp = rt_i*4 + bpair
    const int tid  = threadIdx.x;
    const int half = blockIdx.x & 1;
    const int rt0  = (blockIdx.x >> 1) * 4;

    {
        int rt_i = tid >> 6, rem = tid & 63;
        float4 hv = __ldcg(&((const float4*)g_hout)[((rt0 + rt_i) * 2 + half) * 64 + rem]);
        int b = rem >> 3, kq = (rem & 7) * 4;
        int cp = rt_i * 4 + (b >> 1), hf = b & 1;
        ((float*)&hp[kq + 0][cp])[hf] = hv.x;
        ((float*)&hp[kq + 1][cp])[hf] = hv.y;
        ((float*)&hp[kq + 2][cp])[hf] = hv.z;
        ((float*)&hp[kq + 3][cp])[hf] = hv.w;
    }
    __syncthreads();

    for (int v = tid; v < NVOCAB; v += 256) {
        u64 acc[16];
        const u64 bia = dup2(__ldg(&b_out[v]));
        #pragma unroll
        for (int cp = 0; cp < 16; ++cp) acc[cp] = bia;
        #pragma unroll
        for (int k = 0; k < 32; ++k) {
            const u64 wv = dup2(__ldg(&g_wvt[k * NVOCAB + v]));
            const ulonglong2* hk = (const ulonglong2*)hp[k];
            #pragma unroll
            for (int qq = 0; qq < 8; ++qq) {
                ulonglong2 h2 = hk[qq];
                acc[2 * qq + 0] = fma2(wv, h2.x, acc[2 * qq + 0]);
                acc[2 * qq + 1] = fma2(wv, h2.y, acc[2 * qq + 1]);
            }
        }
        #pragma unroll
        for (int cp = 0; cp < 16; ++cp) {
            int rt_i = cp >> 2, bpp = cp & 3;
            long rt = rt0 + rt_i;
            long bb0 = half * 8 + 2 * bpp;
            float2 o = unpk(acc[cp]);
            outp[(bb0 * (NROWS * NT) + rt) * NVOCAB + v] = o.x;
            outp[((bb0 + 1) * (NROWS * NT) + rt) * NVOCAB + v] = o.y;
        }
    }
}

// ---------------- launch ----------------
extern "C" void kernel_launch(void* const* d_in, const int* in_sizes, int n_in,
                              void* d_out, int out_size)
{
    (void)in_sizes; (void)n_in; (void)out_size;
    const int*   x     = (const int*)  d_in[0];
    const float* embed = (const float*)d_in[1];
    const float* wih0  = (const float*)d_in[2];
    const float* whh0  = (const float*)d_in[3];
    const float* bih0  = (const float*)d_in[4];
    const float* bhh0  = (const float*)d_in[5];
    const float* wih1  = (const float*)d_in[6];
    const float* whh1  = (const float*)d_in[7];
    const float* bih1  = (const float*)d_in[8];
    const float* bhh1  = (const float*)d_in[9];
    const float* wih2  = (const float*)d_in[10];
    const float* whh2  = (const float*)d_in[11];
    const float* bih2  = (const float*)d_in[12];
    const float* bhh2  = (const float*)d_in[13];
    const float* w_h2e = (const float*)d_in[14];
    const float* b_h2e = (const float*)d_in[15];
    const float* w_out = (const float*)d_in[16];
    const float* b_out = (const float*)d_in[17];
    float* outp = (float*)d_out;

    static int smem_set = 0;
    if (!smem_set) {
        cudaFuncSetAttribute(rnn_kernel, cudaFuncAttributeMaxDynamicSharedMemorySize, SMEM_RNN);
        smem_set = 1;
    }

    prep_kernel<<<260, 96>>>(embed, wih0, whh0, wih1, whh1, wih2, whh2,
                             w_h2e, b_h2e, bih0, w_out);
    rnn_kernel<<<NROWS * 2, 128, SMEM_RNN>>>(x, bhh0, bih1, bhh1, bih2, bhh2);
    out_kernel<<<(NROWS * NT / 4) * 2, 256>>>(outp, b_out);
    reset_kernel<<<1, 256>>>();
}